// round 1
// baseline (speedup 1.0000x reference)
#include <cuda_runtime.h>

// Problem constants (fixed by setup_inputs)
#define NU 100000          // n_users
#define NE 100000          // n_entities
#define NN 200000          // n_nodes = NU + NE
#define C  64              // channels
#define N_HOPS 3

// -------- persistent scratch (static device globals; no allocation) --------
__device__ __align__(16) float g_ent_agg[(size_t)NE * C];    // 25.6 MB
__device__ __align__(16) float g_node_agg[(size_t)NN * C];   // 51.2 MB
__device__ __align__(16) float g_user_new[(size_t)NU * C];   // 25.6 MB
__device__ __align__(16) float g_entity_cur[(size_t)NE * C]; // 25.6 MB
__device__ __align__(16) float g_node_cur[(size_t)NN * C];   // 51.2 MB
__device__ __align__(16) float g_ent_cnt[NE];

// Vectorized fire-and-forget global reduction (sm_90+)
__device__ __forceinline__ void red_add_v4(float* addr, float4 v) {
    asm volatile("red.global.add.v4.f32 [%0], {%1, %2, %3, %4};"
                 :: "l"(addr), "f"(v.x), "f"(v.y), "f"(v.z), "f"(v.w)
                 : "memory");
}

// ---------------------------------------------------------------------------
// init: entity_cur = entity_emb; node_cur = [user_emb; entity_emb];
//       out.user_res = user_emb; out.node_res = node_cur
// ---------------------------------------------------------------------------
__global__ void init_kernel(const float* __restrict__ user_emb,
                            const float* __restrict__ entity_emb,
                            float* __restrict__ out) {
    const size_t total4 = (size_t)NN * C / 4;
    const size_t nu4    = (size_t)NU * C / 4;
    const size_t nres4  = (size_t)NN * C / 4;   // node_res offset in float4 units
    float4*       node_cur4 = (float4*)g_node_cur;
    float4*       ent_cur4  = (float4*)g_entity_cur;
    const float4* ue4 = (const float4*)user_emb;
    const float4* ee4 = (const float4*)entity_emb;
    float4*       out4 = (float4*)out;
    for (size_t i = (size_t)blockIdx.x * blockDim.x + threadIdx.x;
         i < total4; i += (size_t)gridDim.x * blockDim.x) {
        float4 v;
        if (i < nu4) {
            v = ue4[i];
            out4[i] = v;                 // user_res init
        } else {
            v = ee4[i - nu4];
            ent_cur4[i - nu4] = v;       // entity_cur init
        }
        node_cur4[i] = v;
        out4[nres4 + i] = v;             // node_res init
    }
}

// ---------------------------------------------------------------------------
// zero scratch accumulators
// ---------------------------------------------------------------------------
__global__ void zero_kernel() {
    const size_t t1 = (size_t)NE * C / 4;
    const size_t t2 = t1 + (size_t)NN * C / 4;
    const size_t t3 = t2 + (size_t)NU * C / 4;
    const size_t t4 = t3 + NE / 4;
    const float4 z = make_float4(0.f, 0.f, 0.f, 0.f);
    for (size_t i = (size_t)blockIdx.x * blockDim.x + threadIdx.x;
         i < t4; i += (size_t)gridDim.x * blockDim.x) {
        if      (i < t1) ((float4*)g_ent_agg )[i]      = z;
        else if (i < t2) ((float4*)g_node_agg)[i - t1] = z;
        else if (i < t3) ((float4*)g_user_new)[i - t2] = z;
        else             ((float4*)g_ent_cnt )[i - t3] = z;
    }
}

// ---------------------------------------------------------------------------
// entity edge scatter: ent_agg[head] += entity_cur[tail] * weight[type-1]
// 16 threads per edge, float4 per thread
// ---------------------------------------------------------------------------
__global__ void ent_edge_kernel(const int* __restrict__ edge_index,
                                const int* __restrict__ edge_type,
                                const float* __restrict__ weight, int E) {
    int tid = blockIdx.x * blockDim.x + threadIdx.x;
    int e = tid >> 4;
    if (e >= E) return;
    int q = (tid & 15) * 4;
    int head = edge_index[e];
    int tail = edge_index[E + e];
    int t    = edge_type[e] - 1;
    float4 s = *(const float4*)(g_entity_cur + (size_t)tail * C + q);
    float4 w = *(const float4*)(weight + (size_t)t * C + q);
    float4 v = make_float4(s.x * w.x, s.y * w.y, s.z * w.z, s.w * w.w);
    red_add_v4(g_ent_agg + (size_t)head * C + q, v);
    if (q == 0) atomicAdd(g_ent_cnt + head, 1.0f);
}

// ---------------------------------------------------------------------------
// node edge scatter: node_agg[eh] += all_emb[et] * extra_weight[type]
// all_emb = [node_cur[:NU] ; entity_cur].  No counts (divide cancels in l2norm)
// ---------------------------------------------------------------------------
__global__ void node_edge_kernel(const int* __restrict__ eidx,
                                 const int* __restrict__ etype,
                                 const float* __restrict__ extra_weight, int E2) {
    int tid = blockIdx.x * blockDim.x + threadIdx.x;
    int e = tid >> 4;
    if (e >= E2) return;
    int q  = (tid & 15) * 4;
    int eh = eidx[e];
    int et = eidx[E2 + e];
    int t  = etype[e];
    const float* src = (et < NU) ? (g_node_cur + (size_t)et * C)
                                 : (g_entity_cur + (size_t)(et - NU) * C);
    float4 s = *(const float4*)(src + q);
    float4 w = *(const float4*)(extra_weight + (size_t)t * C + q);
    float4 v = make_float4(s.x * w.x, s.y * w.y, s.z * w.z, s.w * w.w);
    red_add_v4(g_node_agg + (size_t)eh * C + q, v);
}

// ---------------------------------------------------------------------------
// implicit-matrix user aggregation: user_new[r] += (ent_agg[c]/cnt[c]) * val
// (division fused here — the only consumer that needs the true mean)
// ---------------------------------------------------------------------------
__global__ void im_kernel(const int* __restrict__ im_row,
                          const int* __restrict__ im_col,
                          const float* __restrict__ im_val, int NNZ) {
    int tid = blockIdx.x * blockDim.x + threadIdx.x;
    int e = tid >> 4;
    if (e >= NNZ) return;
    int q = (tid & 15) * 4;
    int r = im_row[e];
    int c = im_col[e];
    float scale = im_val[e] / fmaxf(g_ent_cnt[c], 1.0f);
    float4 s = *(const float4*)(g_ent_agg + (size_t)c * C + q);
    float4 v = make_float4(s.x * scale, s.y * scale, s.z * scale, s.w * scale);
    red_add_v4(g_user_new + (size_t)r * C + q, v);
}

// ---------------------------------------------------------------------------
// row l2-norm kernels (one warp per 64-float row, float2 per lane)
// ---------------------------------------------------------------------------
__device__ __forceinline__ float warp_sum(float s) {
    #pragma unroll
    for (int o = 16; o; o >>= 1) s += __shfl_xor_sync(0xffffffffu, s, o);
    return s;
}

// entity: entity_cur = l2norm(ent_agg / cnt); optionally also write final output
__global__ void ent_norm_kernel(float* __restrict__ out2) {
    int row = blockIdx.x * (blockDim.x >> 5) + (threadIdx.x >> 5);
    if (row >= NE) return;
    int lane = threadIdx.x & 31;
    size_t idx = (size_t)row * C + lane * 2;
    float2 v = *(const float2*)(g_ent_agg + idx);
    float invc = 1.0f / fmaxf(g_ent_cnt[row], 1.0f);
    v.x *= invc; v.y *= invc;
    float s = warp_sum(v.x * v.x + v.y * v.y);
    float inv = 1.0f / fmaxf(sqrtf(s), 1e-12f);
    float2 o = make_float2(v.x * inv, v.y * inv);
    *(float2*)(g_entity_cur + idx) = o;
    if (out2) *(float2*)(out2 + idx) = o;
}

// node: node_cur = l2norm(node_agg); node_res += node_cur
__global__ void node_norm_kernel(float* __restrict__ res) {
    int row = blockIdx.x * (blockDim.x >> 5) + (threadIdx.x >> 5);
    if (row >= NN) return;
    int lane = threadIdx.x & 31;
    size_t idx = (size_t)row * C + lane * 2;
    float2 v = *(const float2*)(g_node_agg + idx);
    float s = warp_sum(v.x * v.x + v.y * v.y);
    float inv = 1.0f / fmaxf(sqrtf(s), 1e-12f);
    float2 o = make_float2(v.x * inv, v.y * inv);
    *(float2*)(g_node_cur + idx) = o;
    float2 r = *(float2*)(res + idx);
    r.x += o.x; r.y += o.y;
    *(float2*)(res + idx) = r;
}

// user: user_res += l2norm(user_new)
__global__ void user_norm_kernel(float* __restrict__ res) {
    int row = blockIdx.x * (blockDim.x >> 5) + (threadIdx.x >> 5);
    if (row >= NU) return;
    int lane = threadIdx.x & 31;
    size_t idx = (size_t)row * C + lane * 2;
    float2 v = *(const float2*)(g_user_new + idx);
    float s = warp_sum(v.x * v.x + v.y * v.y);
    float inv = 1.0f / fmaxf(sqrtf(s), 1e-12f);
    float2 r = *(float2*)(res + idx);
    r.x += v.x * inv; r.y += v.y * inv;
    *(float2*)(res + idx) = r;
}

// ---------------------------------------------------------------------------
extern "C" void kernel_launch(void* const* d_in, const int* in_sizes, int n_in,
                              void* d_out, int out_size) {
    const float* user_emb     = (const float*)d_in[0];
    const float* entity_emb   = (const float*)d_in[1];
    const float* weight       = (const float*)d_in[2];
    const float* extra_weight = (const float*)d_in[3];
    const float* im_val       = (const float*)d_in[4];
    const int*   edge_index   = (const int*)d_in[5];
    const int*   edge_type    = (const int*)d_in[6];
    const int*   extra_eidx   = (const int*)d_in[7];
    const int*   extra_etype  = (const int*)d_in[8];
    const int*   im_row       = (const int*)d_in[9];
    const int*   im_col       = (const int*)d_in[10];

    const int E   = in_sizes[6];
    const int E2  = in_sizes[8];
    const int NNZ = in_sizes[4];

    float* out      = (float*)d_out;
    float* user_res = out;                      // [NU, C]
    float* ent_out  = out + (size_t)NU * C;     // [NE, C] final entity_emb
    float* node_res = out + (size_t)NN * C;     // [NN, C]

    init_kernel<<<2048, 256>>>(user_emb, entity_emb, out);

    for (int hop = 0; hop < N_HOPS; hop++) {
        zero_kernel<<<2048, 256>>>();
        ent_edge_kernel<<<(E * 16 + 255) / 256, 256>>>(edge_index, edge_type, weight, E);
        node_edge_kernel<<<(E2 * 16 + 255) / 256, 256>>>(extra_eidx, extra_etype, extra_weight, E2);
        im_kernel<<<(NNZ * 16 + 255) / 256, 256>>>(im_row, im_col, im_val, NNZ);
        ent_norm_kernel<<<(NE + 7) / 8, 256>>>(hop == N_HOPS - 1 ? ent_out : nullptr);
        node_norm_kernel<<<(NN + 7) / 8, 256>>>(node_res);
        user_norm_kernel<<<(NU + 7) / 8, 256>>>(user_res);
    }
}